// round 1
// baseline (speedup 1.0000x reference)
#include <cuda_runtime.h>
#include <cstdint>

// FP32->FP16 gate-level emulation, collapsed to integer logic.
// Input:  (R = 2048*1024) rows of 32 floats in {0.0, 1.0}, MSB-first IEEE754 fp32 bits.
// Output: R rows of 16 floats in {0.0, 1.0}, MSB-first fp16 bits.
//
// One warp processes 32 rows:
//   - 32 coalesced LDG.32 sweeps (lane l reads bit l of row j), ballot-packed
//     into a uint32 per row (brev -> standard IEEE bit layout).
//   - integer fp16 conversion logic per lane (lane l owns row l).
//   - 4 coalesced float4 stores via shuffle-based redistribution.

__device__ __forceinline__ unsigned convert_row(unsigned w) {
    unsigned s = w >> 31;
    unsigned e = (w >> 23) & 0xFFu;
    unsigned m = w & 0x7FFFFFu;

    unsigned h;
    if (e == 255u) {
        // nan / inf (reference: nan has mant MSB set)
        h = (s << 15) | (m ? 0x7E00u : 0x7C00u);
    } else if (e < 113u) {
        // underflow -> all-zero (sign cleared too, per reference zero_val)
        h = 0u;
    } else if (e > 142u) {
        // overflow -> signed inf
        h = (s << 15) | 0x7C00u;
    } else {
        unsigned mant10 = m >> 13;            // top 10 mantissa bits
        unsigned L = mant10 & 1u;             // fp32_mant[9]
        unsigned R = (m >> 12) & 1u;          // fp32_mant[10]
        unsigned S = (m & 0xFFFu) != 0u;      // OR(fp32_mant[11:23])
        unsigned round_up = R & (S | L);
        unsigned mant_r = mant10 + round_up;  // 11-bit
        unsigned carry = mant_r >> 10;
        unsigned mant_f = mant_r & 0x3FFu;    // == 0 when carry, matches _and(not_carry, mant)
        unsigned exp5 = (e - 112u + carry) & 31u;  // 5-bit wrap add, matches mux(carry,...)
        h = (s << 15) | (exp5 << 10) | mant_f;
    }
    return h;
}

__global__ void __launch_bounds__(256)
fp32_to_fp16_bits_kernel(const float* __restrict__ in,
                         float* __restrict__ out,
                         int nrows) {
    const int lane = threadIdx.x & 31;
    const int warpId = (int)((blockIdx.x * blockDim.x + threadIdx.x) >> 5);
    const int rowbase = warpId * 32;
    if (rowbase >= nrows) return;

    const float* ip = in + (size_t)rowbase * 32;

    // --- input: pack 32 rows into per-lane uint32 words ---
    unsigned mymask = 0u;
#pragma unroll
    for (int j = 0; j < 32; j++) {
        float v = ip[(size_t)j * 32 + lane];
        unsigned mask = __ballot_sync(0xFFFFFFFFu, v != 0.0f);
        if (lane == j) mymask = mask;
    }
    // mask bit p == pulse[p]; brev -> IEEE754 layout (sign at bit 31)
    unsigned w = __brev(mymask);

    // --- compute: real fp32->fp16 logic (bit-exact vs gate algebra on {0,1}) ---
    unsigned h = convert_row(w);

    // --- output: 512 contiguous floats per warp, float4-coalesced ---
    float4* op = (float4*)(out + (size_t)rowbase * 16);
#pragma unroll
    for (int i = 0; i < 4; i++) {
        // flat float index covered this iter: i*128 + 4*lane .. +3
        unsigned hr = __shfl_sync(0xFFFFFFFFu, h, 8 * i + (lane >> 2));
        int k0 = 4 * (lane & 3);  // starting output-bit index within the row
        float4 f;
        f.x = (float)((hr >> (15 - k0)) & 1u);
        f.y = (float)((hr >> (14 - k0)) & 1u);
        f.z = (float)((hr >> (13 - k0)) & 1u);
        f.w = (float)((hr >> (12 - k0)) & 1u);
        op[(size_t)i * 32 + lane] = f;
    }
}

extern "C" void kernel_launch(void* const* d_in, const int* in_sizes, int n_in,
                              void* d_out, int out_size) {
    const float* in = (const float*)d_in[0];
    float* out = (float*)d_out;

    int nrows = in_sizes[0] / 32;           // 2048*1024 = 2097152
    int nwarps = (nrows + 31) / 32;         // one warp per 32 rows
    int threads = 256;                      // 8 warps per block
    int blocks = (nwarps + 7) / 8;

    fp32_to_fp16_bits_kernel<<<blocks, threads>>>(in, out, nrows);
}